// round 2
// baseline (speedup 1.0000x reference)
#include <cuda_runtime.h>
#include <cuda_bf16.h>

// IIR lfilter (order 8 denominator, 9 taps), direct-form-II-transposed.
// x: (64, 64, 8192) fp32  ->  y = clip(lfilter(x, A, B), -1, 1)
//
// Parallelization: each sequence (M = 4096 rows) is split into NCH chunks.
// Each chunk is computed by one thread, warmed up over WARM preceding samples
// starting from zero state. Slowest pole |r| = 0.95 -> transient after 256
// warmup steps is ~2e-6 relative, far below the 1e-3 threshold.

#define T_LEN  8192
#define M_SEQ  4096
#define NCH    8          // chunks per sequence
#define CHUNK  1024       // T_LEN / NCH
#define WARM   256        // warmup samples (0.95^256 ~ 2e-6)

// One DF2T step. State z0..z7, unclamped y feeds the recurrence.
#define IIR_STEP(xv, yout)                                   \
    do {                                                     \
        float yy = fmaf(b0, (xv), z0);                       \
        z0 = fmaf(-a1, yy, fmaf(b1, (xv), z1));              \
        z1 = fmaf(-a2, yy, fmaf(b2, (xv), z2));              \
        z2 = fmaf(-a3, yy, fmaf(b3, (xv), z3));              \
        z3 = fmaf(-a4, yy, fmaf(b4, (xv), z4));              \
        z4 = fmaf(-a5, yy, fmaf(b5, (xv), z5));              \
        z5 = fmaf(-a6, yy, fmaf(b6, (xv), z6));              \
        z6 = fmaf(-a7, yy, fmaf(b7, (xv), z7));              \
        z7 = fmaf(-a8, yy, b8 * (xv));                       \
        (yout) = yy;                                         \
    } while (0)

__global__ __launch_bounds__(128)
void iir_chunked_kernel(const float* __restrict__ x,
                        const float* __restrict__ Ag,
                        const float* __restrict__ Bg,
                        float* __restrict__ y)
{
    const int tid = blockIdx.x * blockDim.x + threadIdx.x;   // 0 .. M_SEQ*NCH-1
    const int c   = tid >> 12;           // chunk index (warp-uniform: 4096 threads per c)
    const int m   = tid & (M_SEQ - 1);   // sequence index (consecutive across lanes)

    // Normalize coefficients (A[0] divide, matching reference).
    const float inv = 1.0f / __ldg(&Ag[0]);
    const float a1 = __ldg(&Ag[1]) * inv;
    const float a2 = __ldg(&Ag[2]) * inv;
    const float a3 = __ldg(&Ag[3]) * inv;
    const float a4 = __ldg(&Ag[4]) * inv;
    const float a5 = __ldg(&Ag[5]) * inv;
    const float a6 = __ldg(&Ag[6]) * inv;
    const float a7 = __ldg(&Ag[7]) * inv;
    const float a8 = __ldg(&Ag[8]) * inv;
    const float b0 = __ldg(&Bg[0]) * inv;
    const float b1 = __ldg(&Bg[1]) * inv;
    const float b2 = __ldg(&Bg[2]) * inv;
    const float b3 = __ldg(&Bg[3]) * inv;
    const float b4 = __ldg(&Bg[4]) * inv;
    const float b5 = __ldg(&Bg[5]) * inv;
    const float b6 = __ldg(&Bg[6]) * inv;
    const float b7 = __ldg(&Bg[7]) * inv;
    const float b8 = __ldg(&Bg[8]) * inv;

    const float* xp = x + (size_t)m * T_LEN;
    float*       yp = y + (size_t)m * T_LEN;

    float z0 = 0.f, z1 = 0.f, z2 = 0.f, z3 = 0.f,
          z4 = 0.f, z5 = 0.f, z6 = 0.f, z7 = 0.f;

    const int tout   = c * CHUNK;                 // first sample we emit
    const int tstart = (c == 0) ? 0 : tout - WARM;
    const int tend   = tout + CHUNK;

    for (int t = tstart; t < tend; t += 4) {
        const float4 xv = *reinterpret_cast<const float4*>(xp + t);
        float y0, y1, y2, y3;
        IIR_STEP(xv.x, y0);
        IIR_STEP(xv.y, y1);
        IIR_STEP(xv.z, y2);
        IIR_STEP(xv.w, y3);
        if (t >= tout) {                          // warp-uniform branch
            float4 yv;
            yv.x = fminf(fmaxf(y0, -1.0f), 1.0f);
            yv.y = fminf(fmaxf(y1, -1.0f), 1.0f);
            yv.z = fminf(fmaxf(y2, -1.0f), 1.0f);
            yv.w = fminf(fmaxf(y3, -1.0f), 1.0f);
            *reinterpret_cast<float4*>(yp + t) = yv;
        }
    }
}

extern "C" void kernel_launch(void* const* d_in, const int* in_sizes, int n_in,
                              void* d_out, int out_size)
{
    const float* x = (const float*)d_in[0];
    const float* A = (const float*)d_in[1];
    const float* B = (const float*)d_in[2];
    float*       y = (float*)d_out;

    const int threads = M_SEQ * NCH;     // 32768
    const int block   = 128;
    iir_chunked_kernel<<<threads / block, block>>>(x, A, B, y);
}

// round 4
// speedup vs baseline: 1.1489x; 1.1489x over previous
#include <cuda_runtime.h>
#include <cuda_bf16.h>

// IIR lfilter (order-8 denominator, 9 taps), direct-form-II-transposed.
// x: (64, 64, 8192) fp32  ->  y = clip(lfilter(x, A, B), -1, 1)
//
// Parallelization: each of M=4096 sequences split into NCH=8 chunks; each
// chunk computed by one thread with WARM=256 warmup samples from zero state
// (slowest pole 0.95 -> transient ~2e-6, well under 1e-3).
//
// R2/R3: 16-sample software pipeline with 4 rotating float4 prefetch
// buffers (MLP=4) to hide the ~577-cycle DRAM latency that dominated R1.
// (R3 is a resubmit: R2 never ran due to container infra failure.)

#define T_LEN  8192
#define M_SEQ  4096
#define NCH    8          // chunks per sequence
#define CHUNK  1024       // T_LEN / NCH
#define WARM   256        // warmup samples

// One DF2T step. State z0..z7; unclamped y feeds the recurrence.
#define IIR_STEP(xv, yout)                                   \
    do {                                                     \
        float yy = fmaf(b0, (xv), z0);                       \
        z0 = fmaf(-a1, yy, fmaf(b1, (xv), z1));              \
        z1 = fmaf(-a2, yy, fmaf(b2, (xv), z2));              \
        z2 = fmaf(-a3, yy, fmaf(b3, (xv), z3));              \
        z3 = fmaf(-a4, yy, fmaf(b4, (xv), z4));              \
        z4 = fmaf(-a5, yy, fmaf(b5, (xv), z5));              \
        z5 = fmaf(-a6, yy, fmaf(b6, (xv), z6));              \
        z6 = fmaf(-a7, yy, fmaf(b7, (xv), z7));              \
        z7 = fmaf(-a8, yy, b8 * (xv));                       \
        (yout) = yy;                                         \
    } while (0)

// Process one float4 group at time tcur; store clamped output if tcur >= tout.
#define PROC4(buf, tcur)                                                 \
    do {                                                                 \
        float y0, y1, y2, y3;                                            \
        IIR_STEP((buf).x, y0);                                           \
        IIR_STEP((buf).y, y1);                                           \
        IIR_STEP((buf).z, y2);                                           \
        IIR_STEP((buf).w, y3);                                           \
        if ((tcur) >= tout) {           /* warp-uniform */               \
            float4 yv;                                                   \
            yv.x = fminf(fmaxf(y0, -1.0f), 1.0f);                        \
            yv.y = fminf(fmaxf(y1, -1.0f), 1.0f);                        \
            yv.z = fminf(fmaxf(y2, -1.0f), 1.0f);                        \
            yv.w = fminf(fmaxf(y3, -1.0f), 1.0f);                        \
            *reinterpret_cast<float4*>(yp + (tcur)) = yv;                \
        }                                                                \
    } while (0)

__global__ __launch_bounds__(128)
void iir_chunked_kernel(const float* __restrict__ x,
                        const float* __restrict__ Ag,
                        const float* __restrict__ Bg,
                        float* __restrict__ y)
{
    const int tid = blockIdx.x * blockDim.x + threadIdx.x;   // 0 .. M_SEQ*NCH-1
    const int c   = tid >> 12;           // chunk index (warp-uniform)
    const int m   = tid & (M_SEQ - 1);   // sequence index (consecutive lanes)

    // Normalize coefficients (divide by A[0], matching reference).
    const float inv = 1.0f / __ldg(&Ag[0]);
    const float a1 = __ldg(&Ag[1]) * inv;
    const float a2 = __ldg(&Ag[2]) * inv;
    const float a3 = __ldg(&Ag[3]) * inv;
    const float a4 = __ldg(&Ag[4]) * inv;
    const float a5 = __ldg(&Ag[5]) * inv;
    const float a6 = __ldg(&Ag[6]) * inv;
    const float a7 = __ldg(&Ag[7]) * inv;
    const float a8 = __ldg(&Ag[8]) * inv;
    const float b0 = __ldg(&Bg[0]) * inv;
    const float b1 = __ldg(&Bg[1]) * inv;
    const float b2 = __ldg(&Bg[2]) * inv;
    const float b3 = __ldg(&Bg[3]) * inv;
    const float b4 = __ldg(&Bg[4]) * inv;
    const float b5 = __ldg(&Bg[5]) * inv;
    const float b6 = __ldg(&Bg[6]) * inv;
    const float b7 = __ldg(&Bg[7]) * inv;
    const float b8 = __ldg(&Bg[8]) * inv;

    const float* xp = x + (size_t)m * T_LEN;
    float*       yp = y + (size_t)m * T_LEN;

    float z0 = 0.f, z1 = 0.f, z2 = 0.f, z3 = 0.f,
          z4 = 0.f, z5 = 0.f, z6 = 0.f, z7 = 0.f;

    const int tout   = c * CHUNK;                 // first emitted sample
    const int tstart = (c == 0) ? 0 : tout - WARM;
    const int tend   = tout + CHUNK;              // (tend - tstart) % 16 == 0

    // Prime the 4-deep prefetch pipeline (16 samples).
    float4 c0_ = *reinterpret_cast<const float4*>(xp + tstart);
    float4 c1_ = *reinterpret_cast<const float4*>(xp + tstart + 4);
    float4 c2_ = *reinterpret_cast<const float4*>(xp + tstart + 8);
    float4 c3_ = *reinterpret_cast<const float4*>(xp + tstart + 12);

    for (int t = tstart; t < tend; t += 16) {
        // Prefetch address for next iteration (in-bounds clamp; warp-uniform).
        const int tp = (t + 16 < tend) ? (t + 16) : tstart;
        const float4 n0 = *reinterpret_cast<const float4*>(xp + tp);
        const float4 n1 = *reinterpret_cast<const float4*>(xp + tp + 4);
        const float4 n2 = *reinterpret_cast<const float4*>(xp + tp + 8);
        const float4 n3 = *reinterpret_cast<const float4*>(xp + tp + 12);

        PROC4(c0_, t);
        PROC4(c1_, t + 4);
        PROC4(c2_, t + 8);
        PROC4(c3_, t + 12);

        c0_ = n0; c1_ = n1; c2_ = n2; c3_ = n3;
    }
}

extern "C" void kernel_launch(void* const* d_in, const int* in_sizes, int n_in,
                              void* d_out, int out_size)
{
    const float* x = (const float*)d_in[0];
    const float* A = (const float*)d_in[1];
    const float* B = (const float*)d_in[2];
    float*       y = (float*)d_out;

    const int threads = M_SEQ * NCH;     // 32768
    const int block   = 128;
    iir_chunked_kernel<<<threads / block, block>>>(x, A, B, y);
}

// round 6
// speedup vs baseline: 1.1512x; 1.0020x over previous
#include <cuda_runtime.h>
#include <cuda_bf16.h>

// IIR lfilter (order-8, 9 taps), DF2T, chunked-warmup parallelization.
// x: (64, 64, 8192) fp32 -> y = clip(lfilter(x, A, B), -1, 1)
//
// R5: fixes R4's macro-shadowing bug (call-site output var named `yy`
// collided with IIR_STEP's internal temp -> stored garbage). Structure
// unchanged: SMEM transpose staging for fully coalesced global I/O
// (R3 was L1tex-wavefront-bound at L1=69.8% due to 32KB inter-lane stride),
// conflict-free time-major tiles (odd stride 129), register prefetch of the
// next tile to hide DRAM latency behind the compute phase.

#define T_LEN   8192
#define M_SEQ   4096
#define NCH     8          // chunks per sequence
#define CHUNK   1024       // T_LEN / NCH
#define WARM    256        // warmup samples (0.95^256 ~ 2e-6)
#define TT      32         // time-tile
#define STRIDE  129        // SMEM row stride in floats (odd -> conflict-free)

// One DF2T step. State z0..z7; unclamped y feeds the recurrence.
// Internal temp named _iir_y to avoid call-site collisions.
#define IIR_STEP(xv, yout)                                       \
    do {                                                         \
        float _iir_y = fmaf(b0, (xv), z0);                       \
        z0 = fmaf(-a1, _iir_y, fmaf(b1, (xv), z1));              \
        z1 = fmaf(-a2, _iir_y, fmaf(b2, (xv), z2));              \
        z2 = fmaf(-a3, _iir_y, fmaf(b3, (xv), z3));              \
        z3 = fmaf(-a4, _iir_y, fmaf(b4, (xv), z4));              \
        z4 = fmaf(-a5, _iir_y, fmaf(b5, (xv), z5));              \
        z5 = fmaf(-a6, _iir_y, fmaf(b6, (xv), z6));              \
        z6 = fmaf(-a7, _iir_y, fmaf(b7, (xv), z7));              \
        z7 = fmaf(-a8, _iir_y, b8 * (xv));                       \
        (yout) = _iir_y;                                         \
    } while (0)

__global__ __launch_bounds__(128)
void iir_smem_kernel(const float* __restrict__ x,
                     const float* __restrict__ Ag,
                     const float* __restrict__ Bg,
                     float* __restrict__ y)
{
    __shared__ float xs[TT * STRIDE];   // [time][seq], stride 129
    __shared__ float ys[TT * STRIDE];

    const int tid   = threadIdx.x;                 // 0..127 = local sequence
    const int c     = blockIdx.x >> 5;             // chunk index (block-uniform)
    const int mbase = (blockIdx.x & 31) << 7;      // 128 sequences per block

    // Normalize coefficients (divide by A[0], matching reference).
    const float inv = 1.0f / __ldg(&Ag[0]);
    const float a1 = __ldg(&Ag[1]) * inv;
    const float a2 = __ldg(&Ag[2]) * inv;
    const float a3 = __ldg(&Ag[3]) * inv;
    const float a4 = __ldg(&Ag[4]) * inv;
    const float a5 = __ldg(&Ag[5]) * inv;
    const float a6 = __ldg(&Ag[6]) * inv;
    const float a7 = __ldg(&Ag[7]) * inv;
    const float a8 = __ldg(&Ag[8]) * inv;
    const float b0 = __ldg(&Bg[0]) * inv;
    const float b1 = __ldg(&Bg[1]) * inv;
    const float b2 = __ldg(&Bg[2]) * inv;
    const float b3 = __ldg(&Bg[3]) * inv;
    const float b4 = __ldg(&Bg[4]) * inv;
    const float b5 = __ldg(&Bg[5]) * inv;
    const float b6 = __ldg(&Bg[6]) * inv;
    const float b7 = __ldg(&Bg[7]) * inv;
    const float b8 = __ldg(&Bg[8]) * inv;

    // Cooperative tile-I/O indexing: lane group -> (row, time-column).
    const int rl  = tid >> 3;           // local row base 0..15 (rows rl + 16*i)
    const int col = (tid & 7) << 2;     // time column within tile: 0,4,...,28

    const float* xbase = x + (size_t)(mbase + rl) * T_LEN + col;
    float*       ybase = y + (size_t)(mbase + rl) * T_LEN + col;

    const int tout   = c * CHUNK;                  // first emitted sample
    const int tstart = (c == 0) ? 0 : tout - WARM;
    const int tend   = tout + CHUNK;               // multiple of TT

    // ---- prime: load + stage first tile ----
    float4 pf[8];
#pragma unroll
    for (int i = 0; i < 8; i++)
        pf[i] = *reinterpret_cast<const float4*>(xbase + (size_t)i * 16 * T_LEN + tstart);
#pragma unroll
    for (int i = 0; i < 8; i++) {
        const int r = rl + 16 * i;
        xs[(col + 0) * STRIDE + r] = pf[i].x;
        xs[(col + 1) * STRIDE + r] = pf[i].y;
        xs[(col + 2) * STRIDE + r] = pf[i].z;
        xs[(col + 3) * STRIDE + r] = pf[i].w;
    }
    __syncthreads();

    float z0 = 0.f, z1 = 0.f, z2 = 0.f, z3 = 0.f,
          z4 = 0.f, z5 = 0.f, z6 = 0.f, z7 = 0.f;

    for (int t = tstart; t < tend; t += TT) {
        // Prefetch next tile (coalesced; clamped in-bounds on last iter).
        const int tp = (t + TT < tend) ? (t + TT) : tstart;
#pragma unroll
        for (int i = 0; i < 8; i++)
            pf[i] = *reinterpret_cast<const float4*>(xbase + (size_t)i * 16 * T_LEN + tp);

        // ---- compute 32 samples from SMEM (conflict-free lane access) ----
#pragma unroll
        for (int tt = 0; tt < TT; tt++) {
            const float xv = xs[tt * STRIDE + tid];
            float yo;
            IIR_STEP(xv, yo);
            ys[tt * STRIDE + tid] = fminf(fmaxf(yo, -1.0f), 1.0f);
        }
        __syncthreads();   // ys complete; xs consumed

        // ---- coalesced output of this tile (skip warmup tiles) ----
        if (t >= tout) {
#pragma unroll
            for (int i = 0; i < 8; i++) {
                const int r = rl + 16 * i;
                float4 v;
                v.x = ys[(col + 0) * STRIDE + r];
                v.y = ys[(col + 1) * STRIDE + r];
                v.z = ys[(col + 2) * STRIDE + r];
                v.w = ys[(col + 3) * STRIDE + r];
                *reinterpret_cast<float4*>(ybase + (size_t)i * 16 * T_LEN + t) = v;
            }
        }

        // ---- stage prefetched tile into xs ----
#pragma unroll
        for (int i = 0; i < 8; i++) {
            const int r = rl + 16 * i;
            xs[(col + 0) * STRIDE + r] = pf[i].x;
            xs[(col + 1) * STRIDE + r] = pf[i].y;
            xs[(col + 2) * STRIDE + r] = pf[i].z;
            xs[(col + 3) * STRIDE + r] = pf[i].w;
        }
        __syncthreads();   // xs ready; ys free to overwrite
    }
}

extern "C" void kernel_launch(void* const* d_in, const int* in_sizes, int n_in,
                              void* d_out, int out_size)
{
    const float* x = (const float*)d_in[0];
    const float* A = (const float*)d_in[1];
    const float* B = (const float*)d_in[2];
    float*       y = (float*)d_out;

    // 256 blocks x 128 threads: 32 blocks of 128 sequences, x8 chunks.
    iir_smem_kernel<<<(M_SEQ / 128) * NCH, 128>>>(x, A, B, y);
}